// round 16
// baseline (speedup 1.0000x reference)
#include <cuda_runtime.h>

// ---------------------------------------------------------------------------
// CombinedGoalObsNetwork — R15: R11 edge kernels (LTS byte roofline, frozen)
// + MLP: 64-row blocks (grid 512, occ ~42%) + vectorized W-fill (4x LDG.128)
// + R11 inner loop (2 rows x 8 cols, x-prefetch d=1).
// ---------------------------------------------------------------------------

#define F64 64
#define NTASK_MAX  32768
#define NACT_MAX   32768

__device__ __align__(16) float g_h_task[NTASK_MAX * F64];
__device__ __align__(16) float g_tmp   [NTASK_MAX * F64];
__device__ __align__(16) float g_x1    [NTASK_MAX * F64];
__device__ __align__(16) float g_h2    [NACT_MAX  * F64];

// ---------------------------------------------------------------------------
// Init: h_task = x_task ; h2 = x_actor
// ---------------------------------------------------------------------------
__global__ void init_kernel(const float* __restrict__ x_task,
                            const float* __restrict__ x_actor,
                            int n_task, int n_actor)
{
    int tot = gridDim.x * blockDim.x;
    int tid = blockIdx.x * blockDim.x + threadIdx.x;
    int nt4 = n_task * (F64 / 4);
    int na4 = n_actor * (F64 / 4);
    const float4* xt = (const float4*)x_task;
    const float4* xa = (const float4*)x_actor;
    float4* ht = (float4*)g_h_task;
    float4* h2 = (float4*)g_h2;
    for (int i = tid; i < nt4; i += tot) ht[i] = xt[i];
    for (int i = tid; i < na4; i += tot) h2[i] = xa[i];
}

__device__ __forceinline__ void red_add_v4(float* p, float4 v)
{
    asm volatile("red.global.add.v4.f32 [%0], {%1,%2,%3,%4};"
                 :: "l"(p), "f"(v.x), "f"(v.y), "f"(v.z), "f"(v.w)
                 : "memory");
}

// ---------------------------------------------------------------------------
// GINEConv edge kernel (frozen): 16 lanes/edge, float4 per lane.
// ---------------------------------------------------------------------------
__global__ void edge_gine_kernel(const float* __restrict__ x_state,
                                 const float* __restrict__ edge_attr,
                                 const float* __restrict__ We,
                                 const float* __restrict__ be,
                                 const int*   __restrict__ src,
                                 const int*   __restrict__ dst,
                                 int E)
{
    const int lane = threadIdx.x & 15;
    const float4 w0 = __ldg((const float4*)We + lane);
    const float4 w1 = __ldg((const float4*)(We + F64) + lane);
    const float4 bb = __ldg((const float4*)be + lane);

    int g  = (blockIdx.x * blockDim.x + threadIdx.x) >> 4;
    int gs = (gridDim.x * blockDim.x) >> 4;

    #pragma unroll 2
    for (int e = g; e < E; e += gs) {
        const int s = __ldg(src + e);
        const int d = __ldg(dst + e);
        const float2 a = __ldg((const float2*)edge_attr + e);
        const float4 x = __ldg((const float4*)(x_state + (size_t)s * F64) + lane);
        float4 v;
        v.x = fmaxf(fmaf(a.x, w0.x, fmaf(a.y, w1.x, x.x + bb.x)), 0.f);
        v.y = fmaxf(fmaf(a.x, w0.y, fmaf(a.y, w1.y, x.y + bb.y)), 0.f);
        v.z = fmaxf(fmaf(a.x, w0.z, fmaf(a.y, w1.z, x.z + bb.z)), 0.f);
        v.w = fmaxf(fmaf(a.x, w0.w, fmaf(a.y, w1.w, x.w + bb.w)), 0.f);
        red_add_v4(g_h_task + (size_t)d * F64 + lane * 4, v);
    }
}

// ---------------------------------------------------------------------------
// GINConv edge kernel (frozen): gather x1 row, scatter-add.
// ---------------------------------------------------------------------------
__global__ void edge_gin_kernel(const int* __restrict__ src,
                                const int* __restrict__ dst,
                                int E)
{
    const int lane = threadIdx.x & 15;
    int g  = (blockIdx.x * blockDim.x + threadIdx.x) >> 4;
    int gs = (gridDim.x * blockDim.x) >> 4;

    #pragma unroll 2
    for (int e = g; e < E; e += gs) {
        const int s = __ldg(src + e);
        const int d = __ldg(dst + e);
        const float4 v = *((const float4*)(g_x1 + (size_t)s * F64) + lane);
        red_add_v4(g_h2 + (size_t)d * F64 + lane * 4, v);
    }
}

// ---------------------------------------------------------------------------
// W SMEM: 8 octant regions at stride 516 floats (512 data + 4 pad).
// Fast fill: 4 coalesced LDG.128 + 4 STS.128 per thread (no scalar chain).
//   float4 i covers W[k][c..c+3], k=i>>4, c=(i&15)*4 -> region o=c>>3, j=c&7.
// ---------------------------------------------------------------------------
#define OSTRIDE 516

__device__ __forceinline__ void fill_w8_fast(float* sW, const float* __restrict__ W, int t)
{
    #pragma unroll
    for (int it = 0; it < 4; it++) {
        const int i = t + it * 256;
        const float4 w = __ldg((const float4*)W + i);
        const int k = i >> 4;
        const int c = (i & 15) * 4;
        const int o = c >> 3, j = c & 7;
        *(float4*)&sW[o * OSTRIDE + k * 8 + j] = w;
    }
}

#define FMA4(acc, xk, wv4)                 \
    (acc)[0] = fmaf(xk, wv4.x, (acc)[0]);  \
    (acc)[1] = fmaf(xk, wv4.y, (acc)[1]);  \
    (acc)[2] = fmaf(xk, wv4.z, (acc)[2]);  \
    (acc)[3] = fmaf(xk, wv4.w, (acc)[3]);

// ---------------------------------------------------------------------------
// Dense 64x64 layer. Block = 256 threads / 64 rows (grid = n/64).
// Thread (rp = t>>3 in 0..31, o = t&7): rows rp, rp+32 ; cols [8o, 8o+8).
// x prefetch d=1; vectorized W fill.
// ---------------------------------------------------------------------------
__global__ void mlp_layer_kernel(const float* __restrict__ in,
                                 const float* __restrict__ W,
                                 const float* __restrict__ b,
                                 float* __restrict__ out,
                                 int n, int do_relu)
{
    __shared__ float sW[8 * OSTRIDE];
    __shared__ float sb[F64];

    const int t = threadIdx.x;
    fill_w8_fast(sW, W, t);
    if (t < F64) sb[t] = b[t];
    __syncthreads();

    const int o  = t & 7;
    const int rp = t >> 3;                 // 0..31
    const int row_base = blockIdx.x * 64;
    int gr0 = row_base + rp;
    int gr1 = row_base + rp + 32;
    const bool v0 = (gr0 < n), v1 = (gr1 < n);
    if (!v0) gr0 = n - 1;
    if (!v1) gr1 = n - 1;

    const float4* x0p = (const float4*)(in + (size_t)gr0 * F64);
    const float4* x1p = (const float4*)(in + (size_t)gr1 * F64);

    float a0[8], a1[8];
    #pragma unroll
    for (int j = 0; j < 8; j++) {
        const float bj = sb[o * 8 + j];
        a0[j] = bj; a1[j] = bj;
    }

    const float* wq = sW + o * OSTRIDE;

    float4 c0 = __ldg(x0p);
    float4 c1 = __ldg(x1p);

    #pragma unroll
    for (int k4 = 0; k4 < 16; k4++) {
        float4 n0, n1;
        if (k4 < 15) {
            n0 = __ldg(x0p + k4 + 1);
            n1 = __ldg(x1p + k4 + 1);
        }
        #pragma unroll
        for (int kk = 0; kk < 4; kk++) {
            const float f0 = (kk==0)?c0.x:(kk==1)?c0.y:(kk==2)?c0.z:c0.w;
            const float f1 = (kk==0)?c1.x:(kk==1)?c1.y:(kk==2)?c1.z:c1.w;
            const float* wr = wq + (k4 * 4 + kk) * 8;
            const float4 wA = *(const float4*)(wr);
            const float4 wB = *(const float4*)(wr + 4);
            FMA4(a0,       f0, wA);  FMA4((a0 + 4), f0, wB);
            FMA4(a1,       f1, wA);  FMA4((a1 + 4), f1, wB);
        }
        if (k4 < 15) { c0 = n0; c1 = n1; }
    }

    if (v0) {
        float4* op = (float4*)(out + (size_t)gr0 * F64) + o * 2;
        #pragma unroll
        for (int i = 0; i < 2; i++) {
            float4 v = make_float4(a0[4*i+0], a0[4*i+1], a0[4*i+2], a0[4*i+3]);
            if (do_relu) { v.x=fmaxf(v.x,0.f); v.y=fmaxf(v.y,0.f); v.z=fmaxf(v.z,0.f); v.w=fmaxf(v.w,0.f); }
            op[i] = v;
        }
    }
    if (v1) {
        float4* op = (float4*)(out + (size_t)gr1 * F64) + o * 2;
        #pragma unroll
        for (int i = 0; i < 2; i++) {
            float4 v = make_float4(a1[4*i+0], a1[4*i+1], a1[4*i+2], a1[4*i+3]);
            if (do_relu) { v.x=fmaxf(v.x,0.f); v.y=fmaxf(v.y,0.f); v.z=fmaxf(v.z,0.f); v.w=fmaxf(v.w,0.f); }
            op[i] = v;
        }
    }
}

// ---------------------------------------------------------------------------
// Fused MLP + head: out[row] = relu(in @ W2a + b2a) @ W2b + b2b (64 -> 1)
// Same 64-row blocks + fast fill + prefetch; 8-lane xor shfl-reduce epilogue.
// ---------------------------------------------------------------------------
__global__ void mlp_head_kernel(const float* __restrict__ in,
                                const float* __restrict__ Wa,
                                const float* __restrict__ ba,
                                const float* __restrict__ wv,
                                const float* __restrict__ bv,
                                float* __restrict__ out, int n)
{
    __shared__ float sW[8 * OSTRIDE];
    __shared__ float sb[F64];
    __shared__ float sw[F64];

    const int t = threadIdx.x;
    fill_w8_fast(sW, Wa, t);
    if (t < F64) { sb[t] = ba[t]; sw[t] = wv[t]; }
    __syncthreads();

    const int o  = t & 7;
    const int rp = t >> 3;
    const int row_base = blockIdx.x * 64;
    int gr0 = row_base + rp;
    int gr1 = row_base + rp + 32;
    const bool v0 = (gr0 < n), v1 = (gr1 < n);
    if (!v0) gr0 = n - 1;
    if (!v1) gr1 = n - 1;

    const float4* x0p = (const float4*)(in + (size_t)gr0 * F64);
    const float4* x1p = (const float4*)(in + (size_t)gr1 * F64);

    float a0[8], a1[8];
    #pragma unroll
    for (int j = 0; j < 8; j++) {
        const float bj = sb[o * 8 + j];
        a0[j] = bj; a1[j] = bj;
    }

    const float* wq = sW + o * OSTRIDE;

    float4 c0 = __ldg(x0p);
    float4 c1 = __ldg(x1p);

    #pragma unroll
    for (int k4 = 0; k4 < 16; k4++) {
        float4 n0, n1;
        if (k4 < 15) {
            n0 = __ldg(x0p + k4 + 1);
            n1 = __ldg(x1p + k4 + 1);
        }
        #pragma unroll
        for (int kk = 0; kk < 4; kk++) {
            const float f0 = (kk==0)?c0.x:(kk==1)?c0.y:(kk==2)?c0.z:c0.w;
            const float f1 = (kk==0)?c1.x:(kk==1)?c1.y:(kk==2)?c1.z:c1.w;
            const float* wr = wq + (k4 * 4 + kk) * 8;
            const float4 wA = *(const float4*)(wr);
            const float4 wB = *(const float4*)(wr + 4);
            FMA4(a0,       f0, wA);  FMA4((a0 + 4), f0, wB);
            FMA4(a1,       f1, wA);  FMA4((a1 + 4), f1, wB);
        }
        if (k4 < 15) { c0 = n0; c1 = n1; }
    }

    float s0 = 0.f, s1 = 0.f;
    #pragma unroll
    for (int j = 0; j < 8; j++) {
        const float w = sw[o * 8 + j];
        s0 = fmaf(fmaxf(a0[j], 0.f), w, s0);
        s1 = fmaf(fmaxf(a1[j], 0.f), w, s1);
    }
    #pragma unroll
    for (int m = 1; m < 8; m <<= 1) {
        s0 += __shfl_xor_sync(0xffffffffu, s0, m, 32);
        s1 += __shfl_xor_sync(0xffffffffu, s1, m, 32);
    }

    if (o == 0) {
        const float bias = __ldg(bv);
        if (v0) out[gr0] = s0 + bias;
        if (v1) out[gr1] = s1 + bias;
    }
}

// ---------------------------------------------------------------------------
static inline int imin(int a, int b) { return a < b ? a : b; }

extern "C" void kernel_launch(void* const* d_in, const int* in_sizes, int n_in,
                              void* d_out, int out_size)
{
    const float* x_state   = (const float*)d_in[0];
    const float* x_task    = (const float*)d_in[1];
    const float* x_actor   = (const float*)d_in[2];
    const float* edge_attr = (const float*)d_in[3];
    const float* We  = (const float*)d_in[4];
    const float* be  = (const float*)d_in[5];
    const float* W1a = (const float*)d_in[6];
    const float* b1a = (const float*)d_in[7];
    const float* W1b = (const float*)d_in[8];
    const float* b1b = (const float*)d_in[9];
    const float* W2a = (const float*)d_in[10];
    const float* b2a = (const float*)d_in[11];
    const float* W2b = (const float*)d_in[12];
    const float* b2b = (const float*)d_in[13];
    const int* src_st = (const int*)d_in[14];
    const int* dst_st = (const int*)d_in[15];
    const int* src_ta = (const int*)d_in[16];
    const int* dst_ta = (const int*)d_in[17];

    const int n_task  = in_sizes[1] / F64;
    const int n_actor = in_sizes[2] / F64;
    const int E_st = in_sizes[14];
    const int E_ta = in_sizes[16];

    float *p_h_task, *p_tmp, *p_x1, *p_h2;
    cudaGetSymbolAddress((void**)&p_h_task, g_h_task);
    cudaGetSymbolAddress((void**)&p_tmp,    g_tmp);
    cudaGetSymbolAddress((void**)&p_x1,     g_x1);
    cudaGetSymbolAddress((void**)&p_h2,     g_h2);

    // 1) residual init
    init_kernel<<<1024, 256>>>(x_task, x_actor, n_task, n_actor);

    // 2) GINEConv message + scatter
    {
        int blocks = imin((E_st * 16 + 255) / 256, 148 * 48);
        edge_gine_kernel<<<blocks, 256>>>(x_state, edge_attr, We, be,
                                          src_st, dst_st, E_st);
    }

    // 3) task MLP: x1 = relu(h @ W1a + b1a) @ W1b + b1b
    {
        int gb = (n_task + 63) / 64;
        mlp_layer_kernel<<<gb, 256>>>(p_h_task, W1a, b1a, p_tmp, n_task, 1);
        mlp_layer_kernel<<<gb, 256>>>(p_tmp,    W1b, b1b, p_x1,  n_task, 0);
    }

    // 4) GINConv gather + scatter
    {
        int blocks = imin((E_ta * 16 + 255) / 256, 148 * 48);
        edge_gin_kernel<<<blocks, 256>>>(src_ta, dst_ta, E_ta);
    }

    // 5) actor MLP + head
    {
        int ga = (n_actor + 63) / 64;
        mlp_head_kernel<<<ga, 256>>>(p_h2, W2a, b2a, W2b, b2b, (float*)d_out, n_actor);
    }
}

// round 17
// speedup vs baseline: 1.0473x; 1.0473x over previous
#include <cuda_runtime.h>

// ---------------------------------------------------------------------------
// CombinedGoalObsNetwork — R16: R11 config (best measured) with:
//   - init kernel replaced by cudaMemsetAsync + residual folded into MLP reads
//   - vectorized W fill (4x LDG.128)
// Edge kernels frozen at LTS byte roofline.
// ---------------------------------------------------------------------------

#define F64 64
#define NTASK_MAX  32768
#define NACT_MAX   32768

__device__ __align__(16) float g_h_task[NTASK_MAX * F64];  // agg (GINE), zeroed
__device__ __align__(16) float g_tmp   [NTASK_MAX * F64];
__device__ __align__(16) float g_x1    [NTASK_MAX * F64];
__device__ __align__(16) float g_h2    [NACT_MAX  * F64];  // agg2 (GIN), zeroed

__device__ __forceinline__ void red_add_v4(float* p, float4 v)
{
    asm volatile("red.global.add.v4.f32 [%0], {%1,%2,%3,%4};"
                 :: "l"(p), "f"(v.x), "f"(v.y), "f"(v.z), "f"(v.w)
                 : "memory");
}

// ---------------------------------------------------------------------------
// GINEConv edge kernel (frozen): 16 lanes/edge, float4 per lane.
// ---------------------------------------------------------------------------
__global__ void edge_gine_kernel(const float* __restrict__ x_state,
                                 const float* __restrict__ edge_attr,
                                 const float* __restrict__ We,
                                 const float* __restrict__ be,
                                 const int*   __restrict__ src,
                                 const int*   __restrict__ dst,
                                 int E)
{
    const int lane = threadIdx.x & 15;
    const float4 w0 = __ldg((const float4*)We + lane);
    const float4 w1 = __ldg((const float4*)(We + F64) + lane);
    const float4 bb = __ldg((const float4*)be + lane);

    int g  = (blockIdx.x * blockDim.x + threadIdx.x) >> 4;
    int gs = (gridDim.x * blockDim.x) >> 4;

    #pragma unroll 2
    for (int e = g; e < E; e += gs) {
        const int s = __ldg(src + e);
        const int d = __ldg(dst + e);
        const float2 a = __ldg((const float2*)edge_attr + e);
        const float4 x = __ldg((const float4*)(x_state + (size_t)s * F64) + lane);
        float4 v;
        v.x = fmaxf(fmaf(a.x, w0.x, fmaf(a.y, w1.x, x.x + bb.x)), 0.f);
        v.y = fmaxf(fmaf(a.x, w0.y, fmaf(a.y, w1.y, x.y + bb.y)), 0.f);
        v.z = fmaxf(fmaf(a.x, w0.z, fmaf(a.y, w1.z, x.z + bb.z)), 0.f);
        v.w = fmaxf(fmaf(a.x, w0.w, fmaf(a.y, w1.w, x.w + bb.w)), 0.f);
        red_add_v4(g_h_task + (size_t)d * F64 + lane * 4, v);
    }
}

// ---------------------------------------------------------------------------
// GINConv edge kernel (frozen): gather x1 row, scatter-add.
// ---------------------------------------------------------------------------
__global__ void edge_gin_kernel(const int* __restrict__ src,
                                const int* __restrict__ dst,
                                int E)
{
    const int lane = threadIdx.x & 15;
    int g  = (blockIdx.x * blockDim.x + threadIdx.x) >> 4;
    int gs = (gridDim.x * blockDim.x) >> 4;

    #pragma unroll 2
    for (int e = g; e < E; e += gs) {
        const int s = __ldg(src + e);
        const int d = __ldg(dst + e);
        const float4 v = *((const float4*)(g_x1 + (size_t)s * F64) + lane);
        red_add_v4(g_h2 + (size_t)d * F64 + lane * 4, v);
    }
}

// ---------------------------------------------------------------------------
// W SMEM: 8 octant regions at stride 516 floats (512 data + 4 pad).
// Vectorized fill: 4 coalesced LDG.128 + 4 STS.128 per thread.
// ---------------------------------------------------------------------------
#define OSTRIDE 516

__device__ __forceinline__ void fill_w8_fast(float* sW, const float* __restrict__ W, int t)
{
    #pragma unroll
    for (int it = 0; it < 4; it++) {
        const int i = t + it * 256;
        const float4 w = __ldg((const float4*)W + i);
        const int k = i >> 4;
        const int c = (i & 15) * 4;
        const int o = c >> 3, j = c & 7;
        *(float4*)&sW[o * OSTRIDE + k * 8 + j] = w;
    }
}

#define FMA4(acc, xk, wv4)                 \
    (acc)[0] = fmaf(xk, wv4.x, (acc)[0]);  \
    (acc)[1] = fmaf(xk, wv4.y, (acc)[1]);  \
    (acc)[2] = fmaf(xk, wv4.z, (acc)[2]);  \
    (acc)[3] = fmaf(xk, wv4.w, (acc)[3]);

__device__ __forceinline__ float4 add4(float4 a, float4 b)
{
    return make_float4(a.x + b.x, a.y + b.y, a.z + b.z, a.w + b.w);
}

// ---------------------------------------------------------------------------
// Dense 64x64 layer (R11 config): block = 256 thr / 128 rows, 4 rows x 8 cols
// per thread, x-prefetch d=1. HAS_RES folds "+ res[row]" into the x stream.
// ---------------------------------------------------------------------------
template <bool HAS_RES>
__global__ void mlp_layer_kernel(const float* __restrict__ in,
                                 const float* __restrict__ res,
                                 const float* __restrict__ W,
                                 const float* __restrict__ b,
                                 float* __restrict__ out,
                                 int n, int do_relu)
{
    __shared__ float sW[8 * OSTRIDE];
    __shared__ float sb[F64];

    const int t = threadIdx.x;
    fill_w8_fast(sW, W, t);
    if (t < F64) sb[t] = b[t];
    __syncthreads();

    const int o  = t & 7;
    const int rp = t >> 3;
    const int row_base = blockIdx.x * 128;

    const size_t rw0 = (size_t)(row_base + rp      ) * F64;
    const size_t rw1 = (size_t)(row_base + rp + 32 ) * F64;
    const size_t rw2 = (size_t)(row_base + rp + 64 ) * F64;
    const size_t rw3 = (size_t)(row_base + rp + 96 ) * F64;

    const float4* x0p = (const float4*)(in + rw0);
    const float4* x1p = (const float4*)(in + rw1);
    const float4* x2p = (const float4*)(in + rw2);
    const float4* x3p = (const float4*)(in + rw3);
    const float4* r0p = (const float4*)(res + rw0);
    const float4* r1p = (const float4*)(res + rw1);
    const float4* r2p = (const float4*)(res + rw2);
    const float4* r3p = (const float4*)(res + rw3);

    float a0[8], a1[8], a2[8], a3[8];
    #pragma unroll
    for (int j = 0; j < 8; j++) {
        const float bj = sb[o * 8 + j];
        a0[j] = bj; a1[j] = bj; a2[j] = bj; a3[j] = bj;
    }

    const float* wq = sW + o * OSTRIDE;

    float4 c0 = __ldg(x0p);
    float4 c1 = __ldg(x1p);
    float4 c2 = __ldg(x2p);
    float4 c3 = __ldg(x3p);
    if (HAS_RES) {
        c0 = add4(c0, __ldg(r0p));
        c1 = add4(c1, __ldg(r1p));
        c2 = add4(c2, __ldg(r2p));
        c3 = add4(c3, __ldg(r3p));
    }

    #pragma unroll
    for (int k4 = 0; k4 < 16; k4++) {
        float4 n0, n1, n2, n3;
        if (k4 < 15) {
            n0 = __ldg(x0p + k4 + 1);
            n1 = __ldg(x1p + k4 + 1);
            n2 = __ldg(x2p + k4 + 1);
            n3 = __ldg(x3p + k4 + 1);
            if (HAS_RES) {
                n0 = add4(n0, __ldg(r0p + k4 + 1));
                n1 = add4(n1, __ldg(r1p + k4 + 1));
                n2 = add4(n2, __ldg(r2p + k4 + 1));
                n3 = add4(n3, __ldg(r3p + k4 + 1));
            }
        }
        #pragma unroll
        for (int kk = 0; kk < 4; kk++) {
            const float f0 = (kk==0)?c0.x:(kk==1)?c0.y:(kk==2)?c0.z:c0.w;
            const float f1 = (kk==0)?c1.x:(kk==1)?c1.y:(kk==2)?c1.z:c1.w;
            const float f2 = (kk==0)?c2.x:(kk==1)?c2.y:(kk==2)?c2.z:c2.w;
            const float f3 = (kk==0)?c3.x:(kk==1)?c3.y:(kk==2)?c3.z:c3.w;
            const float* wr = wq + (k4 * 4 + kk) * 8;
            const float4 wA = *(const float4*)(wr);
            const float4 wB = *(const float4*)(wr + 4);
            FMA4(a0,     f0, wA);  FMA4((a0 + 4), f0, wB);
            FMA4(a1,     f1, wA);  FMA4((a1 + 4), f1, wB);
            FMA4(a2,     f2, wA);  FMA4((a2 + 4), f2, wB);
            FMA4(a3,     f3, wA);  FMA4((a3 + 4), f3, wB);
        }
        if (k4 < 15) { c0 = n0; c1 = n1; c2 = n2; c3 = n3; }
    }

    float* accs[4] = {a0, a1, a2, a3};
    #pragma unroll
    for (int rr = 0; rr < 4; rr++) {
        const int gr = row_base + rp + rr * 32;
        if (gr < n) {
            float* a = accs[rr];
            float4* op = (float4*)(out + (size_t)gr * F64) + o * 2;
            #pragma unroll
            for (int i = 0; i < 2; i++) {
                float4 v = make_float4(a[4*i+0], a[4*i+1], a[4*i+2], a[4*i+3]);
                if (do_relu) { v.x=fmaxf(v.x,0.f); v.y=fmaxf(v.y,0.f); v.z=fmaxf(v.z,0.f); v.w=fmaxf(v.w,0.f); }
                op[i] = v;
            }
        }
    }
}

// ---------------------------------------------------------------------------
// Fused MLP + head (R11 config + residual fold): out[row] =
//   relu((agg2[row]+x_actor[row]) @ W2a + b2a) @ W2b + b2b
// ---------------------------------------------------------------------------
__global__ void mlp_head_kernel(const float* __restrict__ in,
                                const float* __restrict__ res,
                                const float* __restrict__ Wa,
                                const float* __restrict__ ba,
                                const float* __restrict__ wv,
                                const float* __restrict__ bv,
                                float* __restrict__ out, int n)
{
    __shared__ float sW[8 * OSTRIDE];
    __shared__ float sb[F64];
    __shared__ float sw[F64];

    const int t = threadIdx.x;
    fill_w8_fast(sW, Wa, t);
    if (t < F64) { sb[t] = ba[t]; sw[t] = wv[t]; }
    __syncthreads();

    const int o  = t & 7;
    const int rp = t >> 3;
    const int row_base = blockIdx.x * 128;

    const size_t rw0 = (size_t)(row_base + rp      ) * F64;
    const size_t rw1 = (size_t)(row_base + rp + 32 ) * F64;
    const size_t rw2 = (size_t)(row_base + rp + 64 ) * F64;
    const size_t rw3 = (size_t)(row_base + rp + 96 ) * F64;

    const float4* x0p = (const float4*)(in + rw0);
    const float4* x1p = (const float4*)(in + rw1);
    const float4* x2p = (const float4*)(in + rw2);
    const float4* x3p = (const float4*)(in + rw3);
    const float4* r0p = (const float4*)(res + rw0);
    const float4* r1p = (const float4*)(res + rw1);
    const float4* r2p = (const float4*)(res + rw2);
    const float4* r3p = (const float4*)(res + rw3);

    float a0[8], a1[8], a2[8], a3[8];
    #pragma unroll
    for (int j = 0; j < 8; j++) {
        const float bj = sb[o * 8 + j];
        a0[j] = bj; a1[j] = bj; a2[j] = bj; a3[j] = bj;
    }

    const float* wq = sW + o * OSTRIDE;

    float4 c0 = add4(__ldg(x0p), __ldg(r0p));
    float4 c1 = add4(__ldg(x1p), __ldg(r1p));
    float4 c2 = add4(__ldg(x2p), __ldg(r2p));
    float4 c3 = add4(__ldg(x3p), __ldg(r3p));

    #pragma unroll
    for (int k4 = 0; k4 < 16; k4++) {
        float4 n0, n1, n2, n3;
        if (k4 < 15) {
            n0 = add4(__ldg(x0p + k4 + 1), __ldg(r0p + k4 + 1));
            n1 = add4(__ldg(x1p + k4 + 1), __ldg(r1p + k4 + 1));
            n2 = add4(__ldg(x2p + k4 + 1), __ldg(r2p + k4 + 1));
            n3 = add4(__ldg(x3p + k4 + 1), __ldg(r3p + k4 + 1));
        }
        #pragma unroll
        for (int kk = 0; kk < 4; kk++) {
            const float f0 = (kk==0)?c0.x:(kk==1)?c0.y:(kk==2)?c0.z:c0.w;
            const float f1 = (kk==0)?c1.x:(kk==1)?c1.y:(kk==2)?c1.z:c1.w;
            const float f2 = (kk==0)?c2.x:(kk==1)?c2.y:(kk==2)?c2.z:c2.w;
            const float f3 = (kk==0)?c3.x:(kk==1)?c3.y:(kk==2)?c3.z:c3.w;
            const float* wr = wq + (k4 * 4 + kk) * 8;
            const float4 wA = *(const float4*)(wr);
            const float4 wB = *(const float4*)(wr + 4);
            FMA4(a0,     f0, wA);  FMA4((a0 + 4), f0, wB);
            FMA4(a1,     f1, wA);  FMA4((a1 + 4), f1, wB);
            FMA4(a2,     f2, wA);  FMA4((a2 + 4), f2, wB);
            FMA4(a3,     f3, wA);  FMA4((a3 + 4), f3, wB);
        }
        if (k4 < 15) { c0 = n0; c1 = n1; c2 = n2; c3 = n3; }
    }

    float s0 = 0.f, s1 = 0.f, s2 = 0.f, s3 = 0.f;
    #pragma unroll
    for (int j = 0; j < 8; j++) {
        const float w = sw[o * 8 + j];
        s0 = fmaf(fmaxf(a0[j], 0.f), w, s0);
        s1 = fmaf(fmaxf(a1[j], 0.f), w, s1);
        s2 = fmaf(fmaxf(a2[j], 0.f), w, s2);
        s3 = fmaf(fmaxf(a3[j], 0.f), w, s3);
    }
    #pragma unroll
    for (int m = 1; m < 8; m <<= 1) {
        s0 += __shfl_xor_sync(0xffffffffu, s0, m, 32);
        s1 += __shfl_xor_sync(0xffffffffu, s1, m, 32);
        s2 += __shfl_xor_sync(0xffffffffu, s2, m, 32);
        s3 += __shfl_xor_sync(0xffffffffu, s3, m, 32);
    }

    if (o == 0) {
        const float bias = __ldg(bv);
        const int g0 = row_base + rp;
        if (g0      < n) out[g0     ] = s0 + bias;
        if (g0 + 32 < n) out[g0 + 32] = s1 + bias;
        if (g0 + 64 < n) out[g0 + 64] = s2 + bias;
        if (g0 + 96 < n) out[g0 + 96] = s3 + bias;
    }
}

// ---------------------------------------------------------------------------
static inline int imin(int a, int b) { return a < b ? a : b; }

extern "C" void kernel_launch(void* const* d_in, const int* in_sizes, int n_in,
                              void* d_out, int out_size)
{
    const float* x_state   = (const float*)d_in[0];
    const float* x_task    = (const float*)d_in[1];
    const float* x_actor   = (const float*)d_in[2];
    const float* edge_attr = (const float*)d_in[3];
    const float* We  = (const float*)d_in[4];
    const float* be  = (const float*)d_in[5];
    const float* W1a = (const float*)d_in[6];
    const float* b1a = (const float*)d_in[7];
    const float* W1b = (const float*)d_in[8];
    const float* b1b = (const float*)d_in[9];
    const float* W2a = (const float*)d_in[10];
    const float* b2a = (const float*)d_in[11];
    const float* W2b = (const float*)d_in[12];
    const float* b2b = (const float*)d_in[13];
    const int* src_st = (const int*)d_in[14];
    const int* dst_st = (const int*)d_in[15];
    const int* src_ta = (const int*)d_in[16];
    const int* dst_ta = (const int*)d_in[17];

    const int n_task  = in_sizes[1] / F64;
    const int n_actor = in_sizes[2] / F64;
    const int E_st = in_sizes[14];
    const int E_ta = in_sizes[16];

    float *p_h_task, *p_tmp, *p_x1, *p_h2;
    cudaGetSymbolAddress((void**)&p_h_task, g_h_task);
    cudaGetSymbolAddress((void**)&p_tmp,    g_tmp);
    cudaGetSymbolAddress((void**)&p_x1,     g_x1);
    cudaGetSymbolAddress((void**)&p_h2,     g_h2);

    // 1) zero the aggregation buffers (residuals folded into MLP reads)
    cudaMemsetAsync(p_h_task, 0, (size_t)n_task  * F64 * sizeof(float));
    cudaMemsetAsync(p_h2,     0, (size_t)n_actor * F64 * sizeof(float));

    // 2) GINEConv message + scatter
    {
        int blocks = imin((E_st * 16 + 255) / 256, 148 * 48);
        edge_gine_kernel<<<blocks, 256>>>(x_state, edge_attr, We, be,
                                          src_st, dst_st, E_st);
    }

    // 3) task MLP: x1 = relu((agg + x_task) @ W1a + b1a) @ W1b + b1b
    {
        int gb = (n_task + 127) / 128;
        mlp_layer_kernel<true ><<<gb, 256>>>(p_h_task, x_task, W1a, b1a, p_tmp, n_task, 1);
        mlp_layer_kernel<false><<<gb, 256>>>(p_tmp, nullptr,  W1b, b1b, p_x1,  n_task, 0);
    }

    // 4) GINConv gather + scatter
    {
        int blocks = imin((E_ta * 16 + 255) / 256, 148 * 48);
        edge_gin_kernel<<<blocks, 256>>>(src_ta, dst_ta, E_ta);
    }

    // 5) actor MLP + head (residual folded)
    {
        int ga = (n_actor + 127) / 128;
        mlp_head_kernel<<<ga, 256>>>(p_h2, x_actor, W2a, b2a, W2b, b2b,
                                     (float*)d_out, n_actor);
    }
}